// round 1
// baseline (speedup 1.0000x reference)
#include <cuda_runtime.h>
#include <cuda_bf16.h>

// ---------------------------------------------------------------------------
// SchNet interaction block, GB300 sm_103a.
// Shapes: B=8, A=512, N=64 neighbors, n_spatial=128, n_filters=256,
//         n_atom=256, n_ang_feat=128.  M_atoms = B*A = 4096.
//
// Pipeline:
//   K1: XF = x @ W_in2f                      [4096,256]
//   K2: per-atom fused:  H = ssp(F@W1+b1); Wf = H@W2+b2;
//       y = sum_n mask_n * Wf[n,:] * XF[neighbor_n,:]   -> Y [4096,256]
//   K3a: T = Y @ W_f2out + b_f2out
//   K3b: out = ssp(T @ W_dense + b_dense + G_i @ W_ang)
//
// All GEMM math uses packed fp32x2 FMA (fma.rn.f32x2) — exact fp32,
// 2x the 3-reg FFMA issue rate on sm_103a.
// ---------------------------------------------------------------------------

#define BDIM 256
#define NB   64      // neighbors per atom
#define KS   128     // n_spatial
#define NF   256     // n_filters == n_atom
#define NATOMS 4096  // B*A
#define CUTOFF 5.0f

// Scratch (device-global; no allocations allowed)
__device__ float g_XF[NATOMS * NF];
__device__ float g_Y [NATOMS * NF];
__device__ float g_T [NATOMS * NF];

// ---- packed f32x2 helpers --------------------------------------------------

__device__ __forceinline__ void fma2(unsigned long long& d,
                                     unsigned long long a,
                                     unsigned long long b) {
    asm("fma.rn.f32x2 %0, %1, %2, %3;" : "=l"(d) : "l"(a), "l"(b), "l"(d));
}

__device__ __forceinline__ unsigned long long pack_dup(float v) {
    unsigned long long r;
    asm("mov.b64 %0, {%1, %1};" : "=l"(r) : "f"(v));
    return r;
}

__device__ __forceinline__ float2 unpack2(unsigned long long u) {
    float2 r;
    asm("mov.b64 {%0, %1}, %2;" : "=f"(r.x), "=f"(r.y) : "l"(u));
    return r;
}

// shifted softplus: log(0.5*exp(v)+0.5)
__device__ __forceinline__ float sspf(float v) {
    float e = __expf(v);
    float r = __logf(fmaf(0.5f, e, 0.5f));
    return (v > 60.0f) ? (v - 0.69314718055994531f) : r;
}

// ---- shared GEMM inner phase ----------------------------------------------
// Accumulates acc[8][4] (8 rows x 8 cols as 4 f32x2 pairs) for
//   C[n0+j][f0+i] += sum_k sA[(n0+j)*K + k] * W[k*256 + f0+i]
// sA: [64][K] row-major in smem.  W: [K][256] row-major in global.
// sW: 8*256 float staging tile in smem.

__device__ __forceinline__ void gemm_phase(
    const float* sA, int K, const float* __restrict__ W,
    float* sW, unsigned long long (&acc)[8][4],
    int tid, int n0, int f0)
{
    for (int k0 = 0; k0 < K; k0 += 8) {
        // stage 8x256 tile of W (rows contiguous)
        #pragma unroll
        for (int idx = tid * 4; idx < 8 * 256; idx += BDIM * 4)
            *(float4*)&sW[idx] = *(const float4*)&W[k0 * 256 + idx];
        __syncthreads();
        #pragma unroll
        for (int kk = 0; kk < 8; ++kk) {
            ulonglong2 bva = *(const ulonglong2*)&sW[kk * 256 + f0];
            ulonglong2 bvb = *(const ulonglong2*)&sW[kk * 256 + f0 + 4];
            #pragma unroll
            for (int j = 0; j < 8; ++j) {
                unsigned long long a2 = pack_dup(sA[(n0 + j) * K + k0 + kk]);
                fma2(acc[j][0], a2, bva.x);
                fma2(acc[j][1], a2, bva.y);
                fma2(acc[j][2], a2, bvb.x);
                fma2(acc[j][3], a2, bvb.y);
            }
        }
        __syncthreads();
    }
}

// ---- K1 / K3: generic 64-row GEMM (optional second accum phase) ------------
// C[row, 0:256] = act( A[row,0:K] @ W + (A2[row,0:K2] @ W2) + bias )

__global__ __launch_bounds__(BDIM, 2)
void gemm64_kernel(const float* __restrict__ A, int K,
                   const float* __restrict__ W,
                   const float* __restrict__ A2, int K2,
                   const float* __restrict__ W2,
                   const float* __restrict__ bias,
                   float* __restrict__ C, int act)
{
    extern __shared__ float smem[];
    float* sA  = smem;               // 64*K
    float* sA2 = sA + 64 * K;        // 64*K2
    float* sW  = sA2 + 64 * K2;      // 8*256

    const int tid = threadIdx.x;
    const int tn  = tid >> 5;
    const int tf  = tid & 31;
    const int n0  = tn * 8;
    const int f0  = tf * 8;
    const int rowblk = blockIdx.x;

    // stage A rows (contiguous block)
    {
        const float* src = A + (size_t)rowblk * 64 * K;
        for (int idx = tid * 4; idx < 64 * K; idx += BDIM * 4)
            *(float4*)&sA[idx] = *(const float4*)&src[idx];
        if (K2 > 0) {
            const float* src2 = A2 + (size_t)rowblk * 64 * K2;
            for (int idx = tid * 4; idx < 64 * K2; idx += BDIM * 4)
                *(float4*)&sA2[idx] = *(const float4*)&src2[idx];
        }
    }
    __syncthreads();

    unsigned long long acc[8][4];
    #pragma unroll
    for (int j = 0; j < 8; ++j)
        #pragma unroll
        for (int i = 0; i < 4; ++i) acc[j][i] = 0ull;

    gemm_phase(sA, K, W, sW, acc, tid, n0, f0);
    if (K2 > 0) gemm_phase(sA2, K2, W2, sW, acc, tid, n0, f0);

    float bb[8];
    if (bias) {
        float4 ba = *(const float4*)&bias[f0];
        float4 bbv = *(const float4*)&bias[f0 + 4];
        bb[0]=ba.x; bb[1]=ba.y; bb[2]=ba.z; bb[3]=ba.w;
        bb[4]=bbv.x; bb[5]=bbv.y; bb[6]=bbv.z; bb[7]=bbv.w;
    } else {
        #pragma unroll
        for (int i = 0; i < 8; ++i) bb[i] = 0.0f;
    }

    #pragma unroll
    for (int j = 0; j < 8; ++j) {
        float w[8];
        #pragma unroll
        for (int i2 = 0; i2 < 4; ++i2) {
            float2 v = unpack2(acc[j][i2]);
            w[2*i2] = v.x + bb[2*i2];
            w[2*i2+1] = v.y + bb[2*i2+1];
        }
        if (act == 1) {
            #pragma unroll
            for (int i = 0; i < 8; ++i) w[i] = sspf(w[i]);
        }
        const int row = rowblk * 64 + n0 + j;
        *(float4*)&C[(size_t)row * 256 + f0]     = make_float4(w[0], w[1], w[2], w[3]);
        *(float4*)&C[(size_t)row * 256 + f0 + 4] = make_float4(w[4], w[5], w[6], w[7]);
    }
}

// ---- K2: fused filter-MLP + gather + neighbor aggregation ------------------
// One CTA per atom (blockIdx.x = b*A + a).

__global__ __launch_bounds__(BDIM, 2)
void fused_filter_kernel(const float* __restrict__ f_ij,
                         const float* __restrict__ r_ij,
                         const float* __restrict__ nmask,
                         const int*   __restrict__ neigh,
                         const float* __restrict__ W1,
                         const float* __restrict__ b1,
                         const float* __restrict__ W2,
                         const float* __restrict__ b2,
                         const float* __restrict__ XF,
                         float* __restrict__ Y)
{
    extern __shared__ float smem[];
    float* sF = smem;                   // 64*128
    float* sH = sF + NB * KS;           // 64*256
    float* sW = sH + NB * NF;           // 8*256  (reused as reduction buffer)
    float* sM = sW + 8 * NF;            // 64
    int*   sR = (int*)(sM + NB);        // 64

    const int atom = blockIdx.x;
    const int tid  = threadIdx.x;
    const int tn   = tid >> 5;
    const int tf   = tid & 31;
    const int n0   = tn * 8;
    const int f0   = tf * 8;

    // stage f_ij tile [64,128], masks, neighbor rows
    {
        const float* src = f_ij + (size_t)atom * (NB * KS);
        #pragma unroll
        for (int idx = tid * 4; idx < NB * KS; idx += BDIM * 4)
            *(float4*)&sF[idx] = *(const float4*)&src[idx];
    }
    if (tid < NB) {
        float r = r_ij[atom * NB + tid];
        float m = nmask[atom * NB + tid];
        sM[tid] = (r <= CUTOFF) ? m : 0.0f;
        sR[tid] = (atom >> 9) * 512 + neigh[atom * NB + tid];  // b*A + idx
    }
    __syncthreads();

    unsigned long long acc[8][4];
    #pragma unroll
    for (int j = 0; j < 8; ++j)
        #pragma unroll
        for (int i = 0; i < 4; ++i) acc[j][i] = 0ull;

    // GEMM1: H = ssp(F @ W1 + b1)
    gemm_phase(sF, KS, W1, sW, acc, tid, n0, f0);
    {
        float4 ba = *(const float4*)&b1[f0];
        float4 bbv = *(const float4*)&b1[f0 + 4];
        float bb[8] = {ba.x, ba.y, ba.z, ba.w, bbv.x, bbv.y, bbv.z, bbv.w};
        #pragma unroll
        for (int j = 0; j < 8; ++j) {
            float h[8];
            #pragma unroll
            for (int i2 = 0; i2 < 4; ++i2) {
                float2 v = unpack2(acc[j][i2]);
                h[2*i2]   = sspf(v.x + bb[2*i2]);
                h[2*i2+1] = sspf(v.y + bb[2*i2+1]);
            }
            *(float4*)&sH[(n0 + j) * NF + f0]     = make_float4(h[0], h[1], h[2], h[3]);
            *(float4*)&sH[(n0 + j) * NF + f0 + 4] = make_float4(h[4], h[5], h[6], h[7]);
        }
    }
    __syncthreads();

    // GEMM2: Wf = H @ W2 (+b2 in epilogue)
    #pragma unroll
    for (int j = 0; j < 8; ++j)
        #pragma unroll
        for (int i = 0; i < 4; ++i) acc[j][i] = 0ull;

    gemm_phase(sH, NF, W2, sW, acc, tid, n0, f0);

    // epilogue: bias, cutoff*mask, gather xf[neighbor], partial reduce over j
    float part[8];
    #pragma unroll
    for (int i = 0; i < 8; ++i) part[i] = 0.0f;
    {
        float4 ba = *(const float4*)&b2[f0];
        float4 bbv = *(const float4*)&b2[f0 + 4];
        float bb[8] = {ba.x, ba.y, ba.z, ba.w, bbv.x, bbv.y, bbv.z, bbv.w};
        #pragma unroll
        for (int j = 0; j < 8; ++j) {
            const int n = n0 + j;
            const float m = sM[n];              // warp-uniform
            if (m != 0.0f) {
                const float* xr = XF + (size_t)sR[n] * NF + f0;
                float4 xa = *(const float4*)xr;
                float4 xb = *(const float4*)(xr + 4);
                float xv[8] = {xa.x, xa.y, xa.z, xa.w, xb.x, xb.y, xb.z, xb.w};
                float w[8];
                #pragma unroll
                for (int i2 = 0; i2 < 4; ++i2) {
                    float2 v = unpack2(acc[j][i2]);
                    w[2*i2] = v.x; w[2*i2+1] = v.y;
                }
                #pragma unroll
                for (int i = 0; i < 8; ++i)
                    part[i] = fmaf(m * (w[i] + bb[i]), xv[i], part[i]);
            }
        }
    }

    // cross-warp reduction via sW buffer (all GEMM reads of sW are done:
    // gemm_phase ends with __syncthreads)
    #pragma unroll
    for (int i = 0; i < 8; ++i)
        sW[tn * NF + f0 + i] = part[i];
    __syncthreads();
    {
        const int f = tid;          // 256 threads, 256 features
        float y = 0.0f;
        #pragma unroll
        for (int g = 0; g < 8; ++g) y += sW[g * NF + f];
        Y[(size_t)atom * NF + f] = y;
    }
}

// ---------------------------------------------------------------------------

extern "C" void kernel_launch(void* const* d_in, const int* in_sizes, int n_in,
                              void* d_out, int out_size)
{
    const float* x        = (const float*)d_in[0];
    const float* r_ij     = (const float*)d_in[1];
    const float* f_ij     = (const float*)d_in[2];
    const float* G_i      = (const float*)d_in[3];
    const float* nmask    = (const float*)d_in[4];
    const int*   neigh    = (const int*)  d_in[5];
    const float* W_in2f   = (const float*)d_in[6];
    const float* W1       = (const float*)d_in[7];
    const float* b1       = (const float*)d_in[8];
    const float* W2       = (const float*)d_in[9];
    const float* b2       = (const float*)d_in[10];
    const float* W_f2out  = (const float*)d_in[11];
    const float* b_f2out  = (const float*)d_in[12];
    const float* W_dense  = (const float*)d_in[13];
    const float* b_dense  = (const float*)d_in[14];
    const float* W_ang    = (const float*)d_in[15];
    float* out = (float*)d_out;

    float *pXF, *pY, *pT;
    cudaGetSymbolAddress((void**)&pXF, g_XF);
    cudaGetSymbolAddress((void**)&pY,  g_Y);
    cudaGetSymbolAddress((void**)&pT,  g_T);

    const size_t smemA    = (size_t)(64 * 256 + 8 * 256) * 4;              // 73,728
    const size_t smemDual = (size_t)(64 * 256 + 64 * 128 + 8 * 256) * 4;   // 106,496
    const size_t smemF    = (size_t)(NB*KS + NB*NF + 8*NF + NB) * 4 + NB*4;// 107,008

    cudaFuncSetAttribute(gemm64_kernel,
                         cudaFuncAttributeMaxDynamicSharedMemorySize, (int)smemDual);
    cudaFuncSetAttribute(fused_filter_kernel,
                         cudaFuncAttributeMaxDynamicSharedMemorySize, (int)smemF);

    // K1: XF = x @ W_in2f
    gemm64_kernel<<<NATOMS / 64, BDIM, smemA>>>(
        x, 256, W_in2f, nullptr, 0, nullptr, nullptr, pXF, 0);

    // K2: fused filter MLP + gather + aggregate
    fused_filter_kernel<<<NATOMS, BDIM, smemF>>>(
        f_ij, r_ij, nmask, neigh, W1, b1, W2, b2, pXF, pY);

    // K3a: T = Y @ W_f2out + b_f2out
    gemm64_kernel<<<NATOMS / 64, BDIM, smemA>>>(
        pY, 256, W_f2out, nullptr, 0, nullptr, b_f2out, pT, 0);

    // K3b: out = ssp(T @ W_dense + b_dense + G_i @ W_ang)
    gemm64_kernel<<<NATOMS / 64, BDIM, smemDual>>>(
        pT, 256, W_dense, G_i, 128, W_ang, b_dense, out, 1);
}